// round 5
// baseline (speedup 1.0000x reference)
#include <cuda_runtime.h>
#include <stdint.h>

// Problem constants (fixed shapes: z_e [32,64,64,64] f32, codebook [512,64] f32)
#define KCODES   512
#define CDIM     64
#define HW       4096          // 64*64
#define ROWPAD   68            // padded floats per codebook row (bank-spread epilogue gather)
#define NTHREADS 512
#define MAXCAND  32

// ---------- packed f32x2 helpers (Blackwell FFMA2 path; 2x fp32 FMA rate) ----------
__device__ __forceinline__ unsigned long long pk2(float lo, float hi) {
    unsigned long long r;
    asm("mov.b64 %0, {%1, %2};" : "=l"(r) : "f"(lo), "f"(hi));
    return r;
}
__device__ __forceinline__ void upk2(unsigned long long v, float& lo, float& hi) {
    asm("mov.b64 {%0, %1}, %2;" : "=f"(lo), "=f"(hi) : "l"(v));
}
__device__ __forceinline__ unsigned long long fma2(unsigned long long a,
                                                   unsigned long long b,
                                                   unsigned long long c) {
    unsigned long long d;
    asm("fma.rn.f32x2 %0, %1, %2, %3;" : "=l"(d) : "l"(a), "l"(b), "l"(c));
    return d;
}
__device__ __forceinline__ unsigned long long add2(unsigned long long a,
                                                   unsigned long long b) {
    unsigned long long d;
    asm("add.rn.f32x2 %0, %1, %2;" : "=l"(d) : "l"(a), "l"(b));
    return d;
}

// Exact emulation of the reference's fp32 distance for one candidate k:
//   dot  = sequential ascending-c fp32 fma chain (GEMM-style accumulation)
//   S    = RN(zn + cn_k)
//   d    = RN(S - 2*dot)    (single rounding: 2*dot is exact, fused subtract)
__device__ __forceinline__ float exact_d(const unsigned long long* zv,
                                         const float* crow, float zn, float cn)
{
    float dot = 0.f;
    #pragma unroll
    for (int c = 0; c < CDIM / 2; c++) {
        float lo, hi;
        upk2(zv[c], lo, hi);
        dot = fmaf(lo, crow[2 * c    ], dot);
        dot = fmaf(hi, crow[2 * c + 1], dot);
    }
    float S = zn + cn;
    return fmaf(-2.f, dot, S);
}

extern __shared__ float s_mem[];   // [KCODES*ROWPAD] codebook rows + [KCODES] norms

__global__ __launch_bounds__(NTHREADS, 1)
void vq_kernel(const float* __restrict__ z,
               const float* __restrict__ cb,
               float* __restrict__ zq,
               float* __restrict__ idx_out,   // may be null
               int n_total)
{
    float* cbs   = s_mem;                     // padded codebook
    float* cnorm = s_mem + KCODES * ROWPAD;   // ||c_k||^2

    // ---- stage codebook into shared (coalesced float4 reads from gmem) ----
    for (int i = threadIdx.x; i < KCODES * (CDIM / 4); i += NTHREADS) {
        int k = i >> 4;            // / (CDIM/4)
        int j = i & 15;            // % (CDIM/4)
        float4 v = reinterpret_cast<const float4*>(cb)[i];
        *reinterpret_cast<float4*>(cbs + k * ROWPAD + j * 4) = v;
    }
    __syncthreads();
    for (int k = threadIdx.x; k < KCODES; k += NTHREADS) {
        const float* r = cbs + k * ROWPAD;
        float s = 0.f;
        #pragma unroll
        for (int c = 0; c < CDIM; c++) s = fmaf(r[c], r[c], s);
        cnorm[k] = s;
    }
    __syncthreads();

    const int stride = gridDim.x * NTHREADS;
    for (int n = blockIdx.x * NTHREADS + threadIdx.x; n < n_total; n += stride) {
        const int b  = n >> 12;          // n / HW
        const int hw = n & (HW - 1);     // n % HW
        const float* zp = z + (size_t)b * (CDIM * HW) + hw;

        // load z vector (strided per channel, coalesced across lanes), pack f32x2
        // zn = fp32 ||z||^2 (order-insensitive for the final argmin: uniform-shift invariance)
        unsigned long long zv[CDIM / 2];
        float zn = 0.f;
        #pragma unroll
        for (int c = 0; c < CDIM / 2; c++) {
            float lo = zp[(2 * c    ) * HW];
            float hi = zp[(2 * c + 1) * HW];
            zn = fmaf(lo, lo, zn);
            zn = fmaf(hi, hi, zn);
            zv[c] = pk2(lo, hi);
        }

        // guard band: ~16-33 ulps of zn; quantization reorders scores by <= ~2 ulp
        const float delta = zn * 2.0e-6f;

        float best   = 3.4e38f;
        float thresh = 3.4e38f;
        int   cand[MAXCAND];
        int   ncand = 0;
        bool  overflow = false;

        // ---- fast pass: f32x2 dot, collect every k within delta of running best ----
        for (int k = 0; k < KCODES; k++) {
            const ulonglong2* row =
                reinterpret_cast<const ulonglong2*>(cbs + k * ROWPAD);  // 16B aligned
            unsigned long long a0 = 0ULL, a1 = 0ULL, a2 = 0ULL, a3 = 0ULL;
            #pragma unroll
            for (int j = 0; j < CDIM / 4; j += 2) {   // 16 steps of 2
                ulonglong2 r0 = row[j];               // LDS.128 broadcast
                ulonglong2 r1 = row[j + 1];
                a0 = fma2(r0.x, zv[2 * j    ], a0);
                a1 = fma2(r0.y, zv[2 * j + 1], a1);
                a2 = fma2(r1.x, zv[2 * j + 2], a2);
                a3 = fma2(r1.y, zv[2 * j + 3], a3);
            }
            a0 = add2(a0, a1);
            a2 = add2(a2, a3);
            a0 = add2(a0, a2);
            float x, y;
            upk2(a0, x, y);
            float dot = x + y;
            float s = fmaf(-2.f, dot, cnorm[k]);      // fast score (no zn, unquantized)
            if (s < thresh) {
                if (ncand < MAXCAND) cand[ncand++] = k;
                else overflow = true;
                if (s < best) { best = s; thresh = s + delta; }
            }
        }

        // ---- refine: exact reference-rounded d for candidates; first-min wins ----
        int bidx = 0;
        float dbest = 3.4e38f;
        if (!overflow) {
            for (int i = 0; i < ncand; i++) {         // cand[] ascending in k
                int k = cand[i];
                float d = exact_d(zv, cbs + k * ROWPAD, zn, cnorm[k]);
                if (d < dbest) { dbest = d; bidx = k; }
            }
        } else {                                       // ~never: full exact scan
            for (int k = 0; k < KCODES; k++) {
                float d = exact_d(zv, cbs + k * ROWPAD, zn, cnorm[k]);
                if (d < dbest) { dbest = d; bidx = k; }
            }
        }

        // ---- write z_q (channel-major scatter; coalesced across lanes per channel) ----
        float* op = zq + (size_t)b * (CDIM * HW) + hw;
        const float* crow = cbs + bidx * ROWPAD;      // padded -> bank-spread gather
        #pragma unroll
        for (int c = 0; c < CDIM; c++) op[c * HW] = crow[c];

        if (idx_out) idx_out[n] = (float)bidx;
    }
}

extern "C" void kernel_launch(void* const* d_in, const int* in_sizes, int n_in,
                              void* d_out, int out_size)
{
    const float* z  = (const float*)d_in[0];   // [32,64,64,64] f32
    const float* cb = (const float*)d_in[1];   // [512,64] f32

    const int n_total = in_sizes[0] / CDIM;    // 131072
    const int zq_elems = in_sizes[0];          // 8388608

    float* zq = (float*)d_out;
    float* idx_out = nullptr;
    if (out_size >= zq_elems + n_total)
        idx_out = (float*)d_out + zq_elems;    // indices (as float) follow z_q

    const int smem_bytes = (KCODES * ROWPAD + KCODES) * (int)sizeof(float); // 141312

    cudaFuncSetAttribute(vq_kernel, cudaFuncAttributeMaxDynamicSharedMemorySize, smem_bytes);

    int sms = 148;
    cudaDeviceGetAttribute(&sms, cudaDevAttrMultiProcessorCount, 0);

    vq_kernel<<<sms, NTHREADS, smem_bytes>>>(z, cb, zq, idx_out, n_total);
}

// round 6
// speedup vs baseline: 1.0972x; 1.0972x over previous
#include <cuda_runtime.h>
#include <stdint.h>

// Problem constants (fixed shapes: z_e [32,64,64,64] f32, codebook [512,64] f32)
#define KCODES   512
#define CDIM     64
#define HW       4096          // 64*64
#define ROWPAD   68            // padded floats per codebook row (bank-spread epilogue gather, 16B-aligned rows)
#define NTHREADS 256
#define MAXCAND  32

// ---------- packed f32x2 helpers (Blackwell FFMA2 path; 2x fp32 FMA rate) ----------
__device__ __forceinline__ unsigned long long pk2(float lo, float hi) {
    unsigned long long r;
    asm("mov.b64 %0, {%1, %2};" : "=l"(r) : "f"(lo), "f"(hi));
    return r;
}
__device__ __forceinline__ void upk2(unsigned long long v, float& lo, float& hi) {
    asm("mov.b64 {%0, %1}, %2;" : "=f"(lo), "=f"(hi) : "l"(v));
}
__device__ __forceinline__ unsigned long long fma2(unsigned long long a,
                                                   unsigned long long b,
                                                   unsigned long long c) {
    unsigned long long d;
    asm("fma.rn.f32x2 %0, %1, %2, %3;" : "=l"(d) : "l"(a), "l"(b), "l"(c));
    return d;
}
__device__ __forceinline__ unsigned long long add2(unsigned long long a,
                                                   unsigned long long b) {
    unsigned long long d;
    asm("add.rn.f32x2 %0, %1, %2;" : "=l"(d) : "l"(a), "l"(b));
    return d;
}

// Exact emulation of the reference's fp32 distance for one candidate k:
//   dot  = sequential ascending-c fp32 fma chain
//   S    = RN(zn + cn_k)
//   d    = RN(S - 2*dot)   (2*dot exact, fused subtract)
// DO NOT change the operation order — it is what gives rel_err 0.0.
__device__ __forceinline__ float exact_d(const unsigned long long* zv,
                                         const float* crow, float zn, float cn)
{
    float dot = 0.f;
    const float2* cr2 = reinterpret_cast<const float2*>(crow);  // rows are 8B aligned (272B pitch)
    #pragma unroll
    for (int c = 0; c < CDIM / 2; c++) {
        float lo, hi;
        upk2(zv[c], lo, hi);
        float2 cc = cr2[c];
        dot = fmaf(lo, cc.x, dot);
        dot = fmaf(hi, cc.y, dot);
    }
    float S = zn + cn;
    return fmaf(-2.f, dot, S);
}

extern __shared__ float s_mem[];   // [KCODES*ROWPAD] codebook rows + [KCODES] norms

__global__ __launch_bounds__(NTHREADS, 1)
void vq_kernel(const float* __restrict__ z,
               const float* __restrict__ cb,
               float* __restrict__ zq,
               float* __restrict__ idx_out,   // may be null
               int n_total)
{
    float* cbs   = s_mem;                     // padded codebook
    float* cnorm = s_mem + KCODES * ROWPAD;   // ||c_k||^2

    // ---- stage codebook into shared (coalesced float4 reads from gmem) ----
    for (int i = threadIdx.x; i < KCODES * (CDIM / 4); i += NTHREADS) {
        int k = i >> 4;            // / (CDIM/4)
        int j = i & 15;            // % (CDIM/4)
        float4 v = reinterpret_cast<const float4*>(cb)[i];
        *reinterpret_cast<float4*>(cbs + k * ROWPAD + j * 4) = v;
    }
    __syncthreads();
    for (int k = threadIdx.x; k < KCODES; k += NTHREADS) {
        const float* r = cbs + k * ROWPAD;
        float s = 0.f;
        #pragma unroll
        for (int c = 0; c < CDIM; c++) s = fmaf(r[c], r[c], s);
        cnorm[k] = s;
    }
    __syncthreads();

    const int half   = n_total >> 1;          // 65536; queries paired (p, p+half)
    const int stride = gridDim.x * NTHREADS;

    for (int p = blockIdx.x * NTHREADS + threadIdx.x; p < half; p += stride) {
        const int n0 = p;
        const int n1 = p + half;
        const int b0 = n0 >> 12, hw0 = n0 & (HW - 1);
        const int b1 = n1 >> 12, hw1 = n1 & (HW - 1);
        const float* zp0 = z + (size_t)b0 * (CDIM * HW) + hw0;
        const float* zp1 = z + (size_t)b1 * (CDIM * HW) + hw1;

        // load both z vectors (coalesced across lanes), pack channel pairs as f32x2
        unsigned long long zv0[CDIM / 2], zv1[CDIM / 2];
        float zn0 = 0.f, zn1 = 0.f;
        #pragma unroll
        for (int c = 0; c < CDIM / 2; c++) {
            float l0 = zp0[(2 * c) * HW], h0 = zp0[(2 * c + 1) * HW];
            float l1 = zp1[(2 * c) * HW], h1 = zp1[(2 * c + 1) * HW];
            zn0 = fmaf(l0, l0, zn0); zn0 = fmaf(h0, h0, zn0);
            zn1 = fmaf(l1, l1, zn1); zn1 = fmaf(h1, h1, zn1);
            zv0[c] = pk2(l0, h0);
            zv1[c] = pk2(l1, h1);
        }

        // guard band: ~16-33 ulps of zn; quantization reorders scores by <= ~2 ulp
        const float delta0 = zn0 * 2.0e-6f;
        const float delta1 = zn1 * 2.0e-6f;

        float best0 = 3.4e38f, thresh0 = 3.4e38f;
        float best1 = 3.4e38f, thresh1 = 3.4e38f;
        int cand0[MAXCAND], cand1[MAXCAND];
        int ncand0 = 0, ncand1 = 0;
        bool ovf0 = false, ovf1 = false;

        // ---- fast pass: one shared row load feeds BOTH queries (8 indep FFMA2 chains) ----
        for (int k = 0; k < KCODES; k++) {
            const ulonglong2* row =
                reinterpret_cast<const ulonglong2*>(cbs + k * ROWPAD);  // 16B aligned
            unsigned long long a0 = 0ULL, a1 = 0ULL, a2 = 0ULL, a3 = 0ULL;
            unsigned long long c0 = 0ULL, c1 = 0ULL, c2 = 0ULL, c3 = 0ULL;
            #pragma unroll
            for (int j = 0; j < CDIM / 4; j += 2) {   // 8 steps, 2 LDS.128 per step
                ulonglong2 r0 = row[j];
                ulonglong2 r1 = row[j + 1];
                a0 = fma2(r0.x, zv0[2 * j    ], a0);
                c0 = fma2(r0.x, zv1[2 * j    ], c0);
                a1 = fma2(r0.y, zv0[2 * j + 1], a1);
                c1 = fma2(r0.y, zv1[2 * j + 1], c1);
                a2 = fma2(r1.x, zv0[2 * j + 2], a2);
                c2 = fma2(r1.x, zv1[2 * j + 2], c2);
                a3 = fma2(r1.y, zv0[2 * j + 3], a3);
                c3 = fma2(r1.y, zv1[2 * j + 3], c3);
            }
            a0 = add2(a0, a1); a2 = add2(a2, a3); a0 = add2(a0, a2);
            c0 = add2(c0, c1); c2 = add2(c2, c3); c0 = add2(c0, c2);
            float x0, y0, x1, y1;
            upk2(a0, x0, y0);
            upk2(c0, x1, y1);
            float cn = cnorm[k];
            float s0 = fmaf(-2.f, x0 + y0, cn);       // fast score (no zn, unquantized)
            float s1 = fmaf(-2.f, x1 + y1, cn);
            bool p0 = s0 < thresh0;
            bool p1 = s1 < thresh1;
            if (p0 || p1) {
                if (p0) {
                    if (ncand0 < MAXCAND) cand0[ncand0++] = k; else ovf0 = true;
                    if (s0 < best0) { best0 = s0; thresh0 = s0 + delta0; }
                }
                if (p1) {
                    if (ncand1 < MAXCAND) cand1[ncand1++] = k; else ovf1 = true;
                    if (s1 < best1) { best1 = s1; thresh1 = s1 + delta1; }
                }
            }
        }

        // ---- refine: exact reference-rounded d on candidates; first-min wins ----
        int bidx0 = 0, bidx1 = 0;
        {
            float dbest = 3.4e38f;
            if (!ovf0) {
                for (int i = 0; i < ncand0; i++) {
                    int k = cand0[i];
                    float d = exact_d(zv0, cbs + k * ROWPAD, zn0, cnorm[k]);
                    if (d < dbest) { dbest = d; bidx0 = k; }
                }
            } else {
                for (int k = 0; k < KCODES; k++) {
                    float d = exact_d(zv0, cbs + k * ROWPAD, zn0, cnorm[k]);
                    if (d < dbest) { dbest = d; bidx0 = k; }
                }
            }
        }
        {
            float dbest = 3.4e38f;
            if (!ovf1) {
                for (int i = 0; i < ncand1; i++) {
                    int k = cand1[i];
                    float d = exact_d(zv1, cbs + k * ROWPAD, zn1, cnorm[k]);
                    if (d < dbest) { dbest = d; bidx1 = k; }
                }
            } else {
                for (int k = 0; k < KCODES; k++) {
                    float d = exact_d(zv1, cbs + k * ROWPAD, zn1, cnorm[k]);
                    if (d < dbest) { dbest = d; bidx1 = k; }
                }
            }
        }

        // ---- write z_q (channel-major scatter; coalesced across lanes per channel) ----
        {
            float* op = zq + (size_t)b0 * (CDIM * HW) + hw0;
            const float2* crow = reinterpret_cast<const float2*>(cbs + bidx0 * ROWPAD);
            #pragma unroll
            for (int c = 0; c < CDIM / 2; c++) {
                float2 v = crow[c];
                op[(2 * c) * HW]     = v.x;
                op[(2 * c + 1) * HW] = v.y;
            }
        }
        {
            float* op = zq + (size_t)b1 * (CDIM * HW) + hw1;
            const float2* crow = reinterpret_cast<const float2*>(cbs + bidx1 * ROWPAD);
            #pragma unroll
            for (int c = 0; c < CDIM / 2; c++) {
                float2 v = crow[c];
                op[(2 * c) * HW]     = v.x;
                op[(2 * c + 1) * HW] = v.y;
            }
        }

        if (idx_out) {
            idx_out[n0] = (float)bidx0;
            idx_out[n1] = (float)bidx1;
        }
    }
}

extern "C" void kernel_launch(void* const* d_in, const int* in_sizes, int n_in,
                              void* d_out, int out_size)
{
    const float* z  = (const float*)d_in[0];   // [32,64,64,64] f32
    const float* cb = (const float*)d_in[1];   // [512,64] f32

    const int n_total  = in_sizes[0] / CDIM;   // 131072
    const int zq_elems = in_sizes[0];          // 8388608

    float* zq = (float*)d_out;
    float* idx_out = nullptr;
    if (out_size >= zq_elems + n_total)
        idx_out = (float*)d_out + zq_elems;    // indices (as float) follow z_q

    const int smem_bytes = (KCODES * ROWPAD + KCODES) * (int)sizeof(float); // 141312

    cudaFuncSetAttribute(vq_kernel, cudaFuncAttributeMaxDynamicSharedMemorySize, smem_bytes);

    int sms = 148;
    cudaDeviceGetAttribute(&sms, cudaDevAttrMultiProcessorCount, 0);

    vq_kernel<<<sms, NTHREADS, smem_bytes>>>(z, cb, zq, idx_out, n_total);
}

// round 7
// speedup vs baseline: 1.1042x; 1.0064x over previous
#include <cuda_runtime.h>
#include <stdint.h>

// Problem constants (fixed shapes: z_e [32,64,64,64] f32, codebook [512,64] f32)
#define KCODES   512
#define CDIM     64
#define HW       4096          // 64*64
#define ROWPAD   68            // padded floats per row: 272B pitch = 17 ulonglong2, 16B-aligned rows
#define NTHREADS 256

// ---------- packed f32x2 helpers (Blackwell FFMA2 path; 2x fp32 FMA rate) ----------
__device__ __forceinline__ unsigned long long pk2(float lo, float hi) {
    unsigned long long r;
    asm("mov.b64 %0, {%1, %2};" : "=l"(r) : "f"(lo), "f"(hi));
    return r;
}
__device__ __forceinline__ void upk2(unsigned long long v, float& lo, float& hi) {
    asm("mov.b64 {%0, %1}, %2;" : "=f"(lo), "=f"(hi) : "l"(v));
}
__device__ __forceinline__ unsigned long long fma2(unsigned long long a,
                                                   unsigned long long b,
                                                   unsigned long long c) {
    unsigned long long d;
    asm("fma.rn.f32x2 %0, %1, %2, %3;" : "=l"(d) : "l"(a), "l"(b), "l"(c));
    return d;
}
__device__ __forceinline__ unsigned long long add2(unsigned long long a,
                                                   unsigned long long b) {
    unsigned long long d;
    asm("add.rn.f32x2 %0, %1, %2;" : "=l"(d) : "l"(a), "l"(b));
    return d;
}

// Exact emulation of the reference's fp32 distance for one candidate k:
//   dot = sequential ascending-c fp32 fma chain; S = RN(zn+cn); d = RN(S - 2*dot)
// DO NOT change the operation order — this is what gives rel_err 0.0.
__device__ __forceinline__ float exact_d(const unsigned long long* zv,
                                         const float* crow, float zn, float cn)
{
    float dot = 0.f;
    const float2* cr2 = reinterpret_cast<const float2*>(crow);
    #pragma unroll
    for (int c = 0; c < CDIM / 2; c++) {
        float lo, hi;
        upk2(zv[c], lo, hi);
        float2 cc = cr2[c];
        dot = fmaf(lo, cc.x, dot);
        dot = fmaf(hi, cc.y, dot);
    }
    float S = zn + cn;
    return fmaf(-2.f, dot, S);
}

extern __shared__ float s_mem[];   // [KCODES*ROWPAD] codebook rows + [KCODES] norms

__global__ __launch_bounds__(NTHREADS, 1)
void vq_kernel(const float* __restrict__ z,
               const float* __restrict__ cb,
               float* __restrict__ zq,
               float* __restrict__ idx_out,   // may be null
               int n_total)
{
    float* cbs   = s_mem;                     // padded codebook
    float* cnorm = s_mem + KCODES * ROWPAD;   // ||c_k||^2

    // ---- stage codebook into shared (coalesced float4 reads from gmem) ----
    for (int i = threadIdx.x; i < KCODES * (CDIM / 4); i += NTHREADS) {
        int k = i >> 4;
        int j = i & 15;
        float4 v = reinterpret_cast<const float4*>(cb)[i];
        *reinterpret_cast<float4*>(cbs + k * ROWPAD + j * 4) = v;
    }
    __syncthreads();
    for (int k = threadIdx.x; k < KCODES; k += NTHREADS) {
        const float* r = cbs + k * ROWPAD;
        float s = 0.f;
        #pragma unroll
        for (int c = 0; c < CDIM; c++) s = fmaf(r[c], r[c], s);
        cnorm[k] = s;
    }
    __syncthreads();

    const int half   = n_total >> 1;          // queries paired (p, p+half)
    const int stride = gridDim.x * NTHREADS;

    for (int p = blockIdx.x * NTHREADS + threadIdx.x; p < half; p += stride) {
        const int n0 = p;
        const int n1 = p + half;
        const int b0 = n0 >> 12, hw0 = n0 & (HW - 1);
        const int b1 = n1 >> 12, hw1 = n1 & (HW - 1);
        const float* zp0 = z + (size_t)b0 * (CDIM * HW) + hw0;
        const float* zp1 = z + (size_t)b1 * (CDIM * HW) + hw1;

        // load both z vectors (coalesced across lanes), pack channel pairs as f32x2
        unsigned long long zv0[CDIM / 2], zv1[CDIM / 2];
        float zn0 = 0.f, zn1 = 0.f;
        #pragma unroll
        for (int c = 0; c < CDIM / 2; c++) {
            float l0 = zp0[(2 * c) * HW], h0 = zp0[(2 * c + 1) * HW];
            float l1 = zp1[(2 * c) * HW], h1 = zp1[(2 * c + 1) * HW];
            zn0 = fmaf(l0, l0, zn0); zn0 = fmaf(h0, h0, zn0);
            zn1 = fmaf(l1, l1, zn1); zn1 = fmaf(h1, h1, zn1);
            zv0[c] = pk2(l0, h0);
            zv1[c] = pk2(l1, h1);
        }

        // guard band: ~16-33 ulps of zn; fp32 quantization reorders scores <= ~2 ulp
        const float delta0 = zn0 * 2.0e-6f;
        const float delta1 = zn1 * 2.0e-6f;

        float best0 = 3.4e38f, thresh0 = 3.4e38f;
        float best1 = 3.4e38f, thresh1 = 3.4e38f;

        unsigned mask0[KCODES / 32];   // candidate bitmasks (local mem, 16 words each)
        unsigned mask1[KCODES / 32];

        // ---- fast pass: software-pipelined LDS (prefetch 2 j-steps ahead) ----
        const ulonglong2* cur = reinterpret_cast<const ulonglong2*>(cbs);  // row pitch 17
        // prime: steps 0 and 1 of row 0
        ulonglong2 A0 = cur[0], A1 = cur[1];   // step s: uses u2 indices 2s, 2s+1
        ulonglong2 B0 = cur[2], B1 = cur[3];

        int k = 0;
        #pragma unroll 1
        for (int kc = 0; kc < KCODES / 32; kc++) {
            unsigned m0 = 0, m1 = 0;
            #pragma unroll 1
            for (int kk = 0; kk < 32; kk++, k++) {
                const ulonglong2* nxt = cur + 17;   // row k+1 (k=511 prefetch stays in-bounds)
                unsigned long long a0 = 0ULL, a1 = 0ULL, a2 = 0ULL, a3 = 0ULL;
                unsigned long long c0 = 0ULL, c1 = 0ULL, c2 = 0ULL, c3 = 0ULL;
                ulonglong2 r0, r1;

                // step 0 (ch 0..7): consume A, prefetch step 2
                r0 = A0; r1 = A1; A0 = cur[4];  A1 = cur[5];
                a0 = fma2(r0.x, zv0[0], a0);  c0 = fma2(r0.x, zv1[0], c0);
                a1 = fma2(r0.y, zv0[1], a1);  c1 = fma2(r0.y, zv1[1], c1);
                a2 = fma2(r1.x, zv0[2], a2);  c2 = fma2(r1.x, zv1[2], c2);
                a3 = fma2(r1.y, zv0[3], a3);  c3 = fma2(r1.y, zv1[3], c3);
                // step 1: consume B, prefetch step 3
                r0 = B0; r1 = B1; B0 = cur[6];  B1 = cur[7];
                a0 = fma2(r0.x, zv0[4], a0);  c0 = fma2(r0.x, zv1[4], c0);
                a1 = fma2(r0.y, zv0[5], a1);  c1 = fma2(r0.y, zv1[5], c1);
                a2 = fma2(r1.x, zv0[6], a2);  c2 = fma2(r1.x, zv1[6], c2);
                a3 = fma2(r1.y, zv0[7], a3);  c3 = fma2(r1.y, zv1[7], c3);
                // step 2: consume A, prefetch step 4
                r0 = A0; r1 = A1; A0 = cur[8];  A1 = cur[9];
                a0 = fma2(r0.x, zv0[8], a0);  c0 = fma2(r0.x, zv1[8], c0);
                a1 = fma2(r0.y, zv0[9], a1);  c1 = fma2(r0.y, zv1[9], c1);
                a2 = fma2(r1.x, zv0[10], a2); c2 = fma2(r1.x, zv1[10], c2);
                a3 = fma2(r1.y, zv0[11], a3); c3 = fma2(r1.y, zv1[11], c3);
                // step 3: consume B, prefetch step 5
                r0 = B0; r1 = B1; B0 = cur[10]; B1 = cur[11];
                a0 = fma2(r0.x, zv0[12], a0); c0 = fma2(r0.x, zv1[12], c0);
                a1 = fma2(r0.y, zv0[13], a1); c1 = fma2(r0.y, zv1[13], c1);
                a2 = fma2(r1.x, zv0[14], a2); c2 = fma2(r1.x, zv1[14], c2);
                a3 = fma2(r1.y, zv0[15], a3); c3 = fma2(r1.y, zv1[15], c3);
                // step 4: consume A, prefetch step 6
                r0 = A0; r1 = A1; A0 = cur[12]; A1 = cur[13];
                a0 = fma2(r0.x, zv0[16], a0); c0 = fma2(r0.x, zv1[16], c0);
                a1 = fma2(r0.y, zv0[17], a1); c1 = fma2(r0.y, zv1[17], c1);
                a2 = fma2(r1.x, zv0[18], a2); c2 = fma2(r1.x, zv1[18], c2);
                a3 = fma2(r1.y, zv0[19], a3); c3 = fma2(r1.y, zv1[19], c3);
                // step 5: consume B, prefetch step 7
                r0 = B0; r1 = B1; B0 = cur[14]; B1 = cur[15];
                a0 = fma2(r0.x, zv0[20], a0); c0 = fma2(r0.x, zv1[20], c0);
                a1 = fma2(r0.y, zv0[21], a1); c1 = fma2(r0.y, zv1[21], c1);
                a2 = fma2(r1.x, zv0[22], a2); c2 = fma2(r1.x, zv1[22], c2);
                a3 = fma2(r1.y, zv0[23], a3); c3 = fma2(r1.y, zv1[23], c3);
                // step 6: consume A, prefetch next row step 0
                r0 = A0; r1 = A1; A0 = nxt[0];  A1 = nxt[1];
                a0 = fma2(r0.x, zv0[24], a0); c0 = fma2(r0.x, zv1[24], c0);
                a1 = fma2(r0.y, zv0[25], a1); c1 = fma2(r0.y, zv1[25], c1);
                a2 = fma2(r1.x, zv0[26], a2); c2 = fma2(r1.x, zv1[26], c2);
                a3 = fma2(r1.y, zv0[27], a3); c3 = fma2(r1.y, zv1[27], c3);
                // step 7: consume B, prefetch next row step 1
                r0 = B0; r1 = B1; B0 = nxt[2];  B1 = nxt[3];
                a0 = fma2(r0.x, zv0[28], a0); c0 = fma2(r0.x, zv1[28], c0);
                a1 = fma2(r0.y, zv0[29], a1); c1 = fma2(r0.y, zv1[29], c1);
                a2 = fma2(r1.x, zv0[30], a2); c2 = fma2(r1.x, zv1[30], c2);
                a3 = fma2(r1.y, zv0[31], a3); c3 = fma2(r1.y, zv1[31], c3);

                cur = nxt;

                a0 = add2(a0, a1); a2 = add2(a2, a3); a0 = add2(a0, a2);
                c0 = add2(c0, c1); c2 = add2(c2, c3); c0 = add2(c0, c2);
                float x0, y0, x1, y1;
                upk2(a0, x0, y0);
                upk2(c0, x1, y1);
                float cn = cnorm[k];
                float s0 = fmaf(-2.f, x0 + y0, cn);
                float s1 = fmaf(-2.f, x1 + y1, cn);

                unsigned bit = 1u << kk;
                m0 |= (s0 < thresh0) ? bit : 0u;     // branchless candidate record
                m1 |= (s1 < thresh1) ? bit : 0u;
                best0 = fminf(best0, s0); thresh0 = best0 + delta0;
                best1 = fminf(best1, s1); thresh1 = best1 + delta1;
            }
            mask0[kc] = m0;
            mask1[kc] = m1;
        }

        // ---- refine: exact reference-rounded d on candidates; first-min wins ----
        int bidx0 = 0, bidx1 = 0;
        {
            float dbest = 3.4e38f;
            #pragma unroll 1
            for (int kc = 0; kc < KCODES / 32; kc++) {
                unsigned m = mask0[kc];
                while (m) {
                    int b = __ffs(m) - 1;
                    m &= m - 1;
                    int kk2 = kc * 32 + b;
                    float d = exact_d(zv0, cbs + kk2 * ROWPAD, zn0, cnorm[kk2]);
                    if (d < dbest) { dbest = d; bidx0 = kk2; }
                }
            }
        }
        {
            float dbest = 3.4e38f;
            #pragma unroll 1
            for (int kc = 0; kc < KCODES / 32; kc++) {
                unsigned m = mask1[kc];
                while (m) {
                    int b = __ffs(m) - 1;
                    m &= m - 1;
                    int kk2 = kc * 32 + b;
                    float d = exact_d(zv1, cbs + kk2 * ROWPAD, zn1, cnorm[kk2]);
                    if (d < dbest) { dbest = d; bidx1 = kk2; }
                }
            }
        }

        // ---- write z_q (channel-major scatter; coalesced across lanes per channel) ----
        {
            float* op = zq + (size_t)b0 * (CDIM * HW) + hw0;
            const float2* crow = reinterpret_cast<const float2*>(cbs + bidx0 * ROWPAD);
            #pragma unroll
            for (int c = 0; c < CDIM / 2; c++) {
                float2 v = crow[c];
                op[(2 * c) * HW]     = v.x;
                op[(2 * c + 1) * HW] = v.y;
            }
        }
        {
            float* op = zq + (size_t)b1 * (CDIM * HW) + hw1;
            const float2* crow = reinterpret_cast<const float2*>(cbs + bidx1 * ROWPAD);
            #pragma unroll
            for (int c = 0; c < CDIM / 2; c++) {
                float2 v = crow[c];
                op[(2 * c) * HW]     = v.x;
                op[(2 * c + 1) * HW] = v.y;
            }
        }

        if (idx_out) {
            idx_out[n0] = (float)bidx0;
            idx_out[n1] = (float)bidx1;
        }
    }
}

extern "C" void kernel_launch(void* const* d_in, const int* in_sizes, int n_in,
                              void* d_out, int out_size)
{
    const float* z  = (const float*)d_in[0];   // [32,64,64,64] f32
    const float* cb = (const float*)d_in[1];   // [512,64] f32

    const int n_total  = in_sizes[0] / CDIM;   // 131072
    const int zq_elems = in_sizes[0];          // 8388608

    float* zq = (float*)d_out;
    float* idx_out = nullptr;
    if (out_size >= zq_elems + n_total)
        idx_out = (float*)d_out + zq_elems;    // indices (as float) follow z_q

    const int smem_bytes = (KCODES * ROWPAD + KCODES) * (int)sizeof(float); // 141312

    cudaFuncSetAttribute(vq_kernel, cudaFuncAttributeMaxDynamicSharedMemorySize, smem_bytes);

    int sms = 148;
    cudaDeviceGetAttribute(&sms, cudaDevAttrMultiProcessorCount, 0);

    vq_kernel<<<sms, NTHREADS, smem_bytes>>>(z, cb, zq, idx_out, n_total);
}

// round 8
// speedup vs baseline: 1.1069x; 1.0024x over previous
#include <cuda_runtime.h>
#include <stdint.h>

// Problem constants (fixed shapes: z_e [32,64,64,64] f32, codebook [512,64] f32)
#define KCODES   512
#define CDIM     64
#define HW       4096          // 64*64
#define ROWPAD   68            // padded floats per row: 272B pitch = 17 ulonglong2, 16B-aligned rows
#define NTHREADS 256

// ---------- packed f32x2 helpers (Blackwell FFMA2 path; 2x fp32 FMA rate) ----------
__device__ __forceinline__ unsigned long long pk2(float lo, float hi) {
    unsigned long long r;
    asm("mov.b64 %0, {%1, %2};" : "=l"(r) : "f"(lo), "f"(hi));
    return r;
}
__device__ __forceinline__ void upk2(unsigned long long v, float& lo, float& hi) {
    asm("mov.b64 {%0, %1}, %2;" : "=f"(lo), "=f"(hi) : "l"(v));
}
__device__ __forceinline__ unsigned long long fma2(unsigned long long a,
                                                   unsigned long long b,
                                                   unsigned long long c) {
    unsigned long long d;
    asm("fma.rn.f32x2 %0, %1, %2, %3;" : "=l"(d) : "l"(a), "l"(b), "l"(c));
    return d;
}
__device__ __forceinline__ unsigned long long add2(unsigned long long a,
                                                   unsigned long long b) {
    unsigned long long d;
    asm("add.rn.f32x2 %0, %1, %2;" : "=l"(d) : "l"(a), "l"(b));
    return d;
}

// Exact emulation of the reference's fp32 distance for one candidate k:
//   dot = sequential ascending-c fp32 fma chain; S = RN(zn+cn); d = RN(S - 2*dot)
// DO NOT change the operation order — this is what gives rel_err 0.0.
__device__ __forceinline__ float exact_d(const unsigned long long* zv,
                                         const float* crow, float zn, float cn)
{
    float dot = 0.f;
    const float2* cr2 = reinterpret_cast<const float2*>(crow);
    #pragma unroll
    for (int c = 0; c < CDIM / 2; c++) {
        float lo, hi;
        upk2(zv[c], lo, hi);
        float2 cc = cr2[c];
        dot = fmaf(lo, cc.x, dot);
        dot = fmaf(hi, cc.y, dot);
    }
    float S = zn + cn;
    return fmaf(-2.f, dot, S);
}

extern __shared__ float s_mem[];   // [KCODES*ROWPAD] codebook rows + [KCODES] norms

__global__ __launch_bounds__(NTHREADS, 1)
void vq_kernel(const float* __restrict__ z,
               const float* __restrict__ cb,
               float* __restrict__ zq,
               float* __restrict__ idx_out,   // may be null
               int n_total)
{
    float* cbs   = s_mem;                     // padded codebook
    float* cnorm = s_mem + KCODES * ROWPAD;   // ||c_k||^2

    // ---- stage codebook into shared (coalesced float4 reads from gmem) ----
    for (int i = threadIdx.x; i < KCODES * (CDIM / 4); i += NTHREADS) {
        int k = i >> 4;
        int j = i & 15;
        float4 v = reinterpret_cast<const float4*>(cb)[i];
        *reinterpret_cast<float4*>(cbs + k * ROWPAD + j * 4) = v;
    }
    __syncthreads();
    for (int k = threadIdx.x; k < KCODES; k += NTHREADS) {
        const float* r = cbs + k * ROWPAD;
        float s = 0.f;
        #pragma unroll
        for (int c = 0; c < CDIM; c++) s = fmaf(r[c], r[c], s);
        cnorm[k] = s;
    }
    __syncthreads();

    const int half   = n_total >> 1;          // queries paired (p, p+half)
    const int stride = gridDim.x * NTHREADS;

    for (int p = blockIdx.x * NTHREADS + threadIdx.x; p < half; p += stride) {
        const int n0 = p;
        const int n1 = p + half;
        const int b0 = n0 >> 12, hw0 = n0 & (HW - 1);
        const int b1 = n1 >> 12, hw1 = n1 & (HW - 1);
        const float* zp0 = z + (size_t)b0 * (CDIM * HW) + hw0;
        const float* zp1 = z + (size_t)b1 * (CDIM * HW) + hw1;

        // load both z vectors (coalesced across lanes), pack channel pairs as f32x2
        unsigned long long zv0[CDIM / 2], zv1[CDIM / 2];
        float zn0 = 0.f, zn1 = 0.f;
        #pragma unroll
        for (int c = 0; c < CDIM / 2; c++) {
            float l0 = zp0[(2 * c) * HW], h0 = zp0[(2 * c + 1) * HW];
            float l1 = zp1[(2 * c) * HW], h1 = zp1[(2 * c + 1) * HW];
            zn0 = fmaf(l0, l0, zn0); zn0 = fmaf(h0, h0, zn0);
            zn1 = fmaf(l1, l1, zn1); zn1 = fmaf(h1, h1, zn1);
            zv0[c] = pk2(l0, h0);
            zv1[c] = pk2(l1, h1);
        }

        // guard band: ~16-33 ulps of zn; fp32 quantization reorders scores <= ~2 ulp
        const float delta0 = zn0 * 2.0e-6f;
        const float delta1 = zn1 * 2.0e-6f;

        float best0 = 3.4e38f, thresh0 = 3.4e38f;
        float best1 = 3.4e38f, thresh1 = 3.4e38f;

        unsigned mask0[KCODES / 32];   // candidate bitmasks (local mem, 16 words each)
        unsigned mask1[KCODES / 32];

        // ---- fast pass: software-pipelined LDS (prefetch 2 j-steps ahead) ----
        const ulonglong2* cur = reinterpret_cast<const ulonglong2*>(cbs);  // row pitch 17
        // prime: steps 0 and 1 of row 0
        ulonglong2 A0 = cur[0], A1 = cur[1];   // step s: uses u2 indices 2s, 2s+1
        ulonglong2 B0 = cur[2], B1 = cur[3];

        int k = 0;
        #pragma unroll 1
        for (int kc = 0; kc < KCODES / 32; kc++) {
            unsigned m0 = 0, m1 = 0;
            #pragma unroll 1
            for (int kk = 0; kk < 32; kk++, k++) {
                const ulonglong2* nxt = cur + 17;   // row k+1 (k=511 prefetch stays in-bounds)
                unsigned long long a0 = 0ULL, a1 = 0ULL, a2 = 0ULL, a3 = 0ULL;
                unsigned long long c0 = 0ULL, c1 = 0ULL, c2 = 0ULL, c3 = 0ULL;
                ulonglong2 r0, r1;

                // step 0 (ch 0..7): consume A, prefetch step 2
                r0 = A0; r1 = A1; A0 = cur[4];  A1 = cur[5];
                a0 = fma2(r0.x, zv0[0], a0);  c0 = fma2(r0.x, zv1[0], c0);
                a1 = fma2(r0.y, zv0[1], a1);  c1 = fma2(r0.y, zv1[1], c1);
                a2 = fma2(r1.x, zv0[2], a2);  c2 = fma2(r1.x, zv1[2], c2);
                a3 = fma2(r1.y, zv0[3], a3);  c3 = fma2(r1.y, zv1[3], c3);
                // step 1: consume B, prefetch step 3
                r0 = B0; r1 = B1; B0 = cur[6];  B1 = cur[7];
                a0 = fma2(r0.x, zv0[4], a0);  c0 = fma2(r0.x, zv1[4], c0);
                a1 = fma2(r0.y, zv0[5], a1);  c1 = fma2(r0.y, zv1[5], c1);
                a2 = fma2(r1.x, zv0[6], a2);  c2 = fma2(r1.x, zv1[6], c2);
                a3 = fma2(r1.y, zv0[7], a3);  c3 = fma2(r1.y, zv1[7], c3);
                // step 2: consume A, prefetch step 4
                r0 = A0; r1 = A1; A0 = cur[8];  A1 = cur[9];
                a0 = fma2(r0.x, zv0[8], a0);  c0 = fma2(r0.x, zv1[8], c0);
                a1 = fma2(r0.y, zv0[9], a1);  c1 = fma2(r0.y, zv1[9], c1);
                a2 = fma2(r1.x, zv0[10], a2); c2 = fma2(r1.x, zv1[10], c2);
                a3 = fma2(r1.y, zv0[11], a3); c3 = fma2(r1.y, zv1[11], c3);
                // step 3: consume B, prefetch step 5
                r0 = B0; r1 = B1; B0 = cur[10]; B1 = cur[11];
                a0 = fma2(r0.x, zv0[12], a0); c0 = fma2(r0.x, zv1[12], c0);
                a1 = fma2(r0.y, zv0[13], a1); c1 = fma2(r0.y, zv1[13], c1);
                a2 = fma2(r1.x, zv0[14], a2); c2 = fma2(r1.x, zv1[14], c2);
                a3 = fma2(r1.y, zv0[15], a3); c3 = fma2(r1.y, zv1[15], c3);
                // step 4: consume A, prefetch step 6
                r0 = A0; r1 = A1; A0 = cur[12]; A1 = cur[13];
                a0 = fma2(r0.x, zv0[16], a0); c0 = fma2(r0.x, zv1[16], c0);
                a1 = fma2(r0.y, zv0[17], a1); c1 = fma2(r0.y, zv1[17], c1);
                a2 = fma2(r1.x, zv0[18], a2); c2 = fma2(r1.x, zv1[18], c2);
                a3 = fma2(r1.y, zv0[19], a3); c3 = fma2(r1.y, zv1[19], c3);
                // step 5: consume B, prefetch step 7
                r0 = B0; r1 = B1; B0 = cur[14]; B1 = cur[15];
                a0 = fma2(r0.x, zv0[20], a0); c0 = fma2(r0.x, zv1[20], c0);
                a1 = fma2(r0.y, zv0[21], a1); c1 = fma2(r0.y, zv1[21], c1);
                a2 = fma2(r1.x, zv0[22], a2); c2 = fma2(r1.x, zv1[22], c2);
                a3 = fma2(r1.y, zv0[23], a3); c3 = fma2(r1.y, zv1[23], c3);
                // step 6: consume A, prefetch next row step 0
                r0 = A0; r1 = A1; A0 = nxt[0];  A1 = nxt[1];
                a0 = fma2(r0.x, zv0[24], a0); c0 = fma2(r0.x, zv1[24], c0);
                a1 = fma2(r0.y, zv0[25], a1); c1 = fma2(r0.y, zv1[25], c1);
                a2 = fma2(r1.x, zv0[26], a2); c2 = fma2(r1.x, zv1[26], c2);
                a3 = fma2(r1.y, zv0[27], a3); c3 = fma2(r1.y, zv1[27], c3);
                // step 7: consume B, prefetch next row step 1
                r0 = B0; r1 = B1; B0 = nxt[2];  B1 = nxt[3];
                a0 = fma2(r0.x, zv0[28], a0); c0 = fma2(r0.x, zv1[28], c0);
                a1 = fma2(r0.y, zv0[29], a1); c1 = fma2(r0.y, zv1[29], c1);
                a2 = fma2(r1.x, zv0[30], a2); c2 = fma2(r1.x, zv1[30], c2);
                a3 = fma2(r1.y, zv0[31], a3); c3 = fma2(r1.y, zv1[31], c3);

                cur = nxt;

                a0 = add2(a0, a1); a2 = add2(a2, a3); a0 = add2(a0, a2);
                c0 = add2(c0, c1); c2 = add2(c2, c3); c0 = add2(c0, c2);
                float x0, y0, x1, y1;
                upk2(a0, x0, y0);
                upk2(c0, x1, y1);
                float cn = cnorm[k];
                float s0 = fmaf(-2.f, x0 + y0, cn);
                float s1 = fmaf(-2.f, x1 + y1, cn);

                unsigned bit = 1u << kk;
                m0 |= (s0 < thresh0) ? bit : 0u;     // branchless candidate record
                m1 |= (s1 < thresh1) ? bit : 0u;
                best0 = fminf(best0, s0); thresh0 = best0 + delta0;
                best1 = fminf(best1, s1); thresh1 = best1 + delta1;
            }
            mask0[kc] = m0;
            mask1[kc] = m1;
        }

        // ---- refine: exact reference-rounded d on candidates; first-min wins ----
        int bidx0 = 0, bidx1 = 0;
        {
            float dbest = 3.4e38f;
            #pragma unroll 1
            for (int kc = 0; kc < KCODES / 32; kc++) {
                unsigned m = mask0[kc];
                while (m) {
                    int b = __ffs(m) - 1;
                    m &= m - 1;
                    int kk2 = kc * 32 + b;
                    float d = exact_d(zv0, cbs + kk2 * ROWPAD, zn0, cnorm[kk2]);
                    if (d < dbest) { dbest = d; bidx0 = kk2; }
                }
            }
        }
        {
            float dbest = 3.4e38f;
            #pragma unroll 1
            for (int kc = 0; kc < KCODES / 32; kc++) {
                unsigned m = mask1[kc];
                while (m) {
                    int b = __ffs(m) - 1;
                    m &= m - 1;
                    int kk2 = kc * 32 + b;
                    float d = exact_d(zv1, cbs + kk2 * ROWPAD, zn1, cnorm[kk2]);
                    if (d < dbest) { dbest = d; bidx1 = kk2; }
                }
            }
        }

        // ---- write z_q (channel-major scatter; coalesced across lanes per channel) ----
        {
            float* op = zq + (size_t)b0 * (CDIM * HW) + hw0;
            const float2* crow = reinterpret_cast<const float2*>(cbs + bidx0 * ROWPAD);
            #pragma unroll
            for (int c = 0; c < CDIM / 2; c++) {
                float2 v = crow[c];
                op[(2 * c) * HW]     = v.x;
                op[(2 * c + 1) * HW] = v.y;
            }
        }
        {
            float* op = zq + (size_t)b1 * (CDIM * HW) + hw1;
            const float2* crow = reinterpret_cast<const float2*>(cbs + bidx1 * ROWPAD);
            #pragma unroll
            for (int c = 0; c < CDIM / 2; c++) {
                float2 v = crow[c];
                op[(2 * c) * HW]     = v.x;
                op[(2 * c + 1) * HW] = v.y;
            }
        }

        if (idx_out) {
            idx_out[n0] = (float)bidx0;
            idx_out[n1] = (float)bidx1;
        }
    }
}

extern "C" void kernel_launch(void* const* d_in, const int* in_sizes, int n_in,
                              void* d_out, int out_size)
{
    const float* z  = (const float*)d_in[0];   // [32,64,64,64] f32
    const float* cb = (const float*)d_in[1];   // [512,64] f32

    const int n_total  = in_sizes[0] / CDIM;   // 131072
    const int zq_elems = in_sizes[0];          // 8388608

    float* zq = (float*)d_out;
    float* idx_out = nullptr;
    if (out_size >= zq_elems + n_total)
        idx_out = (float*)d_out + zq_elems;    // indices (as float) follow z_q

    const int smem_bytes = (KCODES * ROWPAD + KCODES) * (int)sizeof(float); // 141312

    cudaFuncSetAttribute(vq_kernel, cudaFuncAttributeMaxDynamicSharedMemorySize, smem_bytes);

    int sms = 148;
    cudaDeviceGetAttribute(&sms, cudaDevAttrMultiProcessorCount, 0);

    vq_kernel<<<sms, NTHREADS, smem_bytes>>>(z, cb, zq, idx_out, n_total);
}

// round 10
// speedup vs baseline: 1.1481x; 1.0372x over previous
#include <cuda_runtime.h>
#include <cuda_bf16.h>
#include <stdint.h>

// Fixed shapes: z_e [32,64,64,64] f32, codebook [512,64] f32
#define KCODES   512
#define CDIM     64
#define HW       4096
#define NTHREADS 256
#define TILE_M   128
#define CBPAD    66            // fp32 codebook row pad (264B pitch: float2-aligned, bank-spread)

// ---- SMEM layout (offsets within 1024-aligned base) ----
#define A_OFF    0                                // bf16 A tile 128x64, SW128-swizzled, 16384 B
#define B_OFF    16384                            // bf16 B tile 512x64, SW128-swizzled, 65536 B
#define CB_OFF   (B_OFF + KCODES*CDIM*2)          // fp32 padded codebook, 135168 B
#define CN_OFF   (CB_OFF + KCODES*CBPAD*4)        // cnorm, 2048 B
#define EXD_OFF  (CN_OFF + KCODES*4)              // per-(row,parity) sum|z| partials, 1024 B
#define EXM_OFF  (EXD_OFF + TILE_M*2*4)           // candidate masks [row][lane%4][4], 8192 B
#define REGION_BYTES (EXM_OFF + TILE_M*4*4*4)     // 228352
#define SMEM_DYN (REGION_BYTES + 1024)            // + align slack = 229376 (<= 232448 max optin)

#define SWZ(o) ((o) ^ (((o) >> 3) & 0x70))        // SW128 swizzle (XOR bits[6:4] with [9:7])

// ---------------- PTX helpers (all base sm_80/75 features — no 'a'-suffix) ----------------
__device__ __forceinline__ uint32_t smem_to_u32(const void* p) {
    uint32_t a;
    asm("{ .reg .u64 t; cvta.to.shared.u64 t, %1; cvt.u32.u64 %0, t; }" : "=r"(a) : "l"(p));
    return a;
}
#define LDMATRIX_X4(d0, d1, d2, d3, addr) \
    asm volatile("ldmatrix.sync.aligned.m8n8.x4.shared.b16 {%0,%1,%2,%3}, [%4];" \
        : "=r"(d0), "=r"(d1), "=r"(d2), "=r"(d3) : "r"(addr))

__device__ __forceinline__ void mma16816(float* c, const uint32_t* a,
                                         uint32_t b0, uint32_t b1) {
    asm volatile(
        "mma.sync.aligned.m16n8k16.row.col.f32.bf16.bf16.f32 "
        "{%0,%1,%2,%3}, {%4,%5,%6,%7}, {%8,%9}, {%0,%1,%2,%3};"
        : "+f"(c[0]), "+f"(c[1]), "+f"(c[2]), "+f"(c[3])
        : "r"(a[0]), "r"(a[1]), "r"(a[2]), "r"(a[3]), "r"(b0), "r"(b1));
}

// Exact emulation of the reference's fp32 distance (DO NOT reorder — gives rel_err 0.0):
//   dot = ascending-c fp32 fma chain; S = RN(zn + cn); d = RN(S - 2*dot)
__device__ __forceinline__ float exact_d(const float* zr, const float* crow,
                                         float zn, float cn) {
    float dot = 0.f;
    const float2* cr2 = reinterpret_cast<const float2*>(crow);
    #pragma unroll
    for (int c = 0; c < CDIM / 2; c++) {
        float2 cc = cr2[c];
        dot = fmaf(zr[2 * c    ], cc.x, dot);
        dot = fmaf(zr[2 * c + 1], cc.y, dot);
    }
    float S = zn + cn;
    return fmaf(-2.f, dot, S);
}

extern __shared__ char smem_raw[];

__global__ __launch_bounds__(NTHREADS, 1)
void vq_mma_kernel(const float* __restrict__ z,
                   const float* __restrict__ cb,
                   float* __restrict__ zq,
                   float* __restrict__ idx_out,
                   int n_tiles)
{
    const uint32_t smem_u = smem_to_u32(smem_raw);
    const uint32_t base_u = (smem_u + 1023u) & ~1023u;   // 1024-align for SW128
    char* base = smem_raw + (base_u - smem_u);

    float*    cbf32 = reinterpret_cast<float*>(base + CB_OFF);
    float*    cnorm = reinterpret_cast<float*>(base + CN_OFF);
    float*    exd2  = reinterpret_cast<float*>(base + EXD_OFF);
    unsigned* exm   = reinterpret_cast<unsigned*>(base + EXM_OFF);

    const int tid  = threadIdx.x;
    const int wid  = tid >> 5;
    const int lane = tid & 31;
    const int row  = tid & (TILE_M - 1);     // A-load / owner row
    const int par  = tid >> 7;               // 0: even channels, 1: odd channels

    // ---- stage codebook: fp32 padded copy + bf16 SW128 B tile + cnorm (once) ----
    for (int i = tid; i < KCODES * CDIM; i += NTHREADS) {
        int k = i >> 6, c = i & 63;
        float v = cb[i];
        cbf32[k * CBPAD + c] = v;
        *reinterpret_cast<__nv_bfloat16*>(base + B_OFF + SWZ((uint32_t)(k * 128 + c * 2)))
            = __float2bfloat16(v);
    }
    for (int k = tid; k < KCODES; k += NTHREADS) {
        const float* r = cb + k * CDIM;      // ascending-c fma: identical to refine's cn use
        float s = 0.f;
        #pragma unroll
        for (int c = 0; c < CDIM; c++) s = fmaf(r[c], r[c], s);
        cnorm[k] = s;
    }
    __syncthreads();

    float zev[32];                           // owner's even channels, captured during A-load

    for (int t = blockIdx.x; t < n_tiles; t += gridDim.x) {
        const int n0  = t * TILE_M;
        const int b   = n0 >> 12;
        const int hw0 = n0 & (HW - 1);       // 128-tiles never cross a batch boundary
        const float* zb = z + (size_t)b * (CDIM * HW) + hw0;

        // ---- A tile load: thread (row, par) loads channels par, par+2, ... ----
        float sa = 0.f;
        #pragma unroll
        for (int s = 0; s < 32; s++) {
            int c = par + 2 * s;
            float v = zb[c * HW + row];      // coalesced: lanes = consecutive rows
            if (par == 0) zev[s] = v;        // owners keep even channels
            sa += fabsf(v);
            *reinterpret_cast<__nv_bfloat16*>(base + A_OFF + SWZ((uint32_t)(row * 128 + c * 2)))
                = __float2bfloat16(v);
        }
        exd2[row * 2 + par] = sa;
        __syncthreads();

        // ---- A fragments: 4 k-steps, rows 16*wid..16*wid+15 (ldmatrix.x4) ----
        uint32_t af[4][4];
        {
            int r_l  = lane & 15;            // lanes 0-7,16-23 -> rows 0-7; 8-15,24-31 -> 8-15
            int kofs = (lane >> 4) * 8;
            #pragma unroll
            for (int kk = 0; kk < 4; kk++) {
                uint32_t off = (uint32_t)((16 * wid + r_l) * 128 + (16 * kk + kofs) * 2);
                uint32_t addr = base_u + A_OFF + SWZ(off);
                LDMATRIX_X4(af[kk][0], af[kk][1], af[kk][2], af[kk][3], addr);
            }
        }

        // ---- scan: 64 chunks of 8 codes; lane-local running best + candidate bitmask ----
        const int grp = lane >> 2;           // C-fragment row group (0..7)
        const int tq  = lane & 3;            // C-fragment col pair (cols 2tq, 2tq+1)
        const int r0  = 16 * wid + grp;      // global tile row of c0/c1
        const int r1  = r0 + 8;              // global tile row of c2/c3
        const float dlt0 = (exd2[2 * r0] + exd2[2 * r0 + 1]) * 2.5e-5f + 6e-5f;
        const float dlt1 = (exd2[2 * r1] + exd2[2 * r1 + 1]) * 2.5e-5f + 6e-5f;

        float best0 = 3.4e38f, thr0 = 3.4e38f;
        float best1 = 3.4e38f, thr1 = 3.4e38f;
        unsigned mA[4] = {0, 0, 0, 0};       // row r0: 64 chunks x 2 bits
        unsigned mB[4] = {0, 0, 0, 0};       // row r1

        const int bn = lane & 7;             // ldmatrix B row within chunk
        const int bk = (lane >> 3) * 8;      // ldmatrix B k-offset (0,8,16,24)

        #pragma unroll 4
        for (int nc = 0; nc < 64; nc++) {
            // B fragments: ldmatrix.x4 covers k 0..31 (regs 0,1 = kstep0; 2,3 = kstep1)
            uint32_t b0, b1, b2, b3, b4, b5, b6, b7;
            {
                uint32_t off0 = (uint32_t)((nc * 8 + bn) * 128 + bk * 2);
                uint32_t off1 = (uint32_t)((nc * 8 + bn) * 128 + (bk + 32) * 2);
                LDMATRIX_X4(b0, b1, b2, b3, base_u + B_OFF + SWZ(off0));
                LDMATRIX_X4(b4, b5, b6, b7, base_u + B_OFF + SWZ(off1));
            }
            float cfr[4] = {0.f, 0.f, 0.f, 0.f};
            mma16816(cfr, af[0], b0, b1);
            mma16816(cfr, af[1], b2, b3);
            mma16816(cfr, af[2], b4, b5);
            mma16816(cfr, af[3], b6, b7);

            // scores for cols (8nc + 2tq, +1); rows r0 (c0,c1) and r1 (c2,c3)
            float2 cn2 = *reinterpret_cast<const float2*>(&cnorm[nc * 8 + 2 * tq]);
            float s00 = fmaf(-2.f, cfr[0], cn2.x);
            float s01 = fmaf(-2.f, cfr[1], cn2.y);
            float s10 = fmaf(-2.f, cfr[2], cn2.x);
            float s11 = fmaf(-2.f, cfr[3], cn2.y);

            const int w  = nc >> 4;
            const int bi = 2 * (nc & 15);
            mA[w] |= (s00 < thr0) ? (1u << bi)       : 0u;
            mA[w] |= (s01 < thr0) ? (1u << (bi + 1)) : 0u;
            mB[w] |= (s10 < thr1) ? (1u << bi)       : 0u;
            mB[w] |= (s11 < thr1) ? (1u << (bi + 1)) : 0u;
            best0 = fminf(best0, fminf(s00, s01));  thr0 = best0 + dlt0;
            best1 = fminf(best1, fminf(s10, s11));  thr1 = best1 + dlt1;
        }

        // publish masks: exm[(row*4 + tq)*4 + w]
        #pragma unroll
        for (int w = 0; w < 4; w++) {
            exm[(r0 * 4 + tq) * 4 + w] = mA[w];
            exm[(r1 * 4 + tq) * 4 + w] = mB[w];
        }
        __syncthreads();

        // ---- owners (tid<128): exact refine over candidate union, then epilogue ----
        if (par == 0) {
            float zr[CDIM];
            #pragma unroll
            for (int s = 0; s < 32; s++) {
                zr[2 * s]     = zev[s];
                zr[2 * s + 1] = zb[(2 * s + 1) * HW + row];   // L2-hot re-fetch
            }
            float zn = 0.f;
            #pragma unroll
            for (int c = 0; c < CDIM; c++) zn = fmaf(zr[c], zr[c], zn);  // ascending

            int bidx = 0;
            float dbest = 3.4e38f;
            #pragma unroll 1
            for (int w = 0; w < 4; w++) {                    // 128-code blocks
                unsigned m0 = exm[(row * 4 + 0) * 4 + w];
                unsigned m1 = exm[(row * 4 + 1) * 4 + w];
                unsigned m2 = exm[(row * 4 + 2) * 4 + w];
                unsigned m3 = exm[(row * 4 + 3) * 4 + w];
                unsigned any = m0 | m1 | m2 | m3;
                if (!any) continue;
                #pragma unroll 1
                for (int c16 = 0; c16 < 16; c16++) {
                    unsigned sh = 2 * c16;
                    if (!((any >> sh) & 3u)) continue;
                    int kbase = 128 * w + 8 * c16;
                    // ascending k within chunk: lanes tq=0..3 cover cols 2tq, 2tq+1
                    unsigned bb0 = (m0 >> sh) & 3u, bb1 = (m1 >> sh) & 3u;
                    unsigned bb2 = (m2 >> sh) & 3u, bb3 = (m3 >> sh) & 3u;
                    unsigned packed = bb0 | (bb1 << 2) | (bb2 << 4) | (bb3 << 6);
                    while (packed) {
                        int bit = __ffs(packed) - 1;         // ascending col within chunk
                        packed &= packed - 1;
                        int k = kbase + bit;
                        float d = exact_d(zr, cbf32 + k * CBPAD, zn, cnorm[k]);
                        if (d < dbest) { dbest = d; bidx = k; }   // strict <, ascending k
                    }
                }
            }

            // z_q: channel-major scatter, coalesced across 128 owners per channel
            float* op = zq + (size_t)b * (CDIM * HW) + hw0 + row;
            const float2* crow = reinterpret_cast<const float2*>(cbf32 + bidx * CBPAD);
            #pragma unroll
            for (int c = 0; c < CDIM / 2; c++) {
                float2 v = crow[c];
                op[(2 * c) * HW]     = v.x;
                op[(2 * c + 1) * HW] = v.y;
            }
            if (idx_out) idx_out[n0 + row] = (float)bidx;
        }
        __syncthreads();                     // protect A tile + exm before next tile
    }
}

extern "C" void kernel_launch(void* const* d_in, const int* in_sizes, int n_in,
                              void* d_out, int out_size)
{
    const float* z  = (const float*)d_in[0];   // [32,64,64,64] f32
    const float* cb = (const float*)d_in[1];   // [512,64] f32

    const int n_total  = in_sizes[0] / CDIM;   // 131072
    const int zq_elems = in_sizes[0];          // 8388608
    const int n_tiles  = n_total / TILE_M;     // 1024

    float* zq = (float*)d_out;
    float* idx_out = nullptr;
    if (out_size >= zq_elems + n_total)
        idx_out = (float*)d_out + zq_elems;

    cudaFuncSetAttribute(vq_mma_kernel, cudaFuncAttributeMaxDynamicSharedMemorySize, SMEM_DYN);

    int sms = 148;
    cudaDeviceGetAttribute(&sms, cudaDevAttrMultiProcessorCount, 0);

    vq_mma_kernel<<<sms, NTHREADS, SMEM_DYN>>>(z, cb, zq, idx_out, n_tiles);
}